// round 1
// baseline (speedup 1.0000x reference)
#include <cuda_runtime.h>
#include <cstdint>

#define N_NODES_MAX 100000
#define DIM 128

// 51.2 MB scratch for transformed node features (allocation-free rule: __device__ global)
__device__ float g_T[(size_t)N_NODES_MAX * DIM];

// ---------------------------------------------------------------------------
// Kernel 1: T = node_emb @ W^T   (W is [128][128] row-major; T[r][j] = sum_k E[r][k]*W[j][k])
// 128x128 output tile per block, 256 threads, 8x8 register micro-tile, BK=8 smem chunks.
// ---------------------------------------------------------------------------
__global__ __launch_bounds__(256, 2)
void transform_kernel(const float* __restrict__ E, const float* __restrict__ W, int n_rows)
{
    __shared__ float Es[8][132];  // Es[kk][r]  (padded: stride 132 kills bank conflicts)
    __shared__ float Ws[8][132];  // Ws[kk][j] = W[j][k0+kk]

    const int tid  = threadIdx.x;
    const int tx   = tid & 15;      // 16 col-groups
    const int ty   = tid >> 4;      // 16 row-groups
    const int row0 = blockIdx.x * 128;

    float acc[8][8];
#pragma unroll
    for (int i = 0; i < 8; i++)
#pragma unroll
        for (int j = 0; j < 8; j++) acc[i][j] = 0.f;

    for (int k0 = 0; k0 < 128; k0 += 8) {
        __syncthreads();  // protect previous iteration's smem reads
#pragma unroll
        for (int t = 0; t < 4; t++) {
            int idx = tid + t * 256;       // 1024 elements
            int r   = idx >> 3;
            int kk  = idx & 7;
            int row = row0 + r;
            float v = 0.f;
            if (row < n_rows) v = E[(size_t)row * DIM + k0 + kk];
            Es[kk][r] = v;
        }
#pragma unroll
        for (int t = 0; t < 4; t++) {
            int idx = tid + t * 256;
            int j   = idx >> 3;
            int kk  = idx & 7;
            Ws[kk][j] = W[(size_t)j * DIM + k0 + kk];
        }
        __syncthreads();

#pragma unroll
        for (int kk = 0; kk < 8; kk++) {
            float a[8];
#pragma unroll
            for (int i = 0; i < 8; i++) a[i] = Es[kk][ty + 16 * i];
            float4 b0 = *reinterpret_cast<const float4*>(&Ws[kk][tx * 4]);
            float4 b1 = *reinterpret_cast<const float4*>(&Ws[kk][tx * 4 + 64]);
#pragma unroll
            for (int i = 0; i < 8; i++) {
                acc[i][0] += a[i] * b0.x;
                acc[i][1] += a[i] * b0.y;
                acc[i][2] += a[i] * b0.z;
                acc[i][3] += a[i] * b0.w;
                acc[i][4] += a[i] * b1.x;
                acc[i][5] += a[i] * b1.y;
                acc[i][6] += a[i] * b1.z;
                acc[i][7] += a[i] * b1.w;
            }
        }
    }

#pragma unroll
    for (int i = 0; i < 8; i++) {
        int row = row0 + ty + 16 * i;
        if (row < n_rows) {
            float4 v0 = make_float4(acc[i][0], acc[i][1], acc[i][2], acc[i][3]);
            float4 v1 = make_float4(acc[i][4], acc[i][5], acc[i][6], acc[i][7]);
            *reinterpret_cast<float4*>(&g_T[(size_t)row * DIM + tx * 4])      = v0;
            *reinterpret_cast<float4*>(&g_T[(size_t)row * DIM + tx * 4 + 64]) = v1;
        }
    }
}

// ---------------------------------------------------------------------------
// Kernel 2: out[dst[e]] += T[src[e]] * w[e]  (one warp per edge; float4 lanes;
// vectorized L2-side reduction red.global.add.v4.f32 -> 4x fewer atomic ops)
// ---------------------------------------------------------------------------
__global__ __launch_bounds__(256)
void scatter_kernel(const float* __restrict__ ew,
                    const int*   __restrict__ src,
                    const int*   __restrict__ dst,
                    float*       __restrict__ out,
                    int n_edges)
{
    int warp = (int)((blockIdx.x * (unsigned)blockDim.x + threadIdx.x) >> 5);
    int lane = threadIdx.x & 31;
    if (warp >= n_edges) return;

    int   s = __ldg(&src[warp]);
    int   d = __ldg(&dst[warp]);
    float w = __ldg(&ew[warp]);

    float4 v = *reinterpret_cast<const float4*>(&g_T[(size_t)s * DIM + lane * 4]);
    v.x *= w; v.y *= w; v.z *= w; v.w *= w;

    float* o = out + (size_t)d * DIM + lane * 4;
    asm volatile("red.global.add.v4.f32 [%0], {%1, %2, %3, %4};"
                 :: "l"(o), "f"(v.x), "f"(v.y), "f"(v.z), "f"(v.w)
                 : "memory");
}

// ---------------------------------------------------------------------------
// Launch: inputs (metadata order): node_emb f32[100000*128], edge_weight f32[E],
//         src i32[E], dst i32[E], W f32[128*128]. Output f32[100000*128].
// ---------------------------------------------------------------------------
extern "C" void kernel_launch(void* const* d_in, const int* in_sizes, int n_in,
                              void* d_out, int out_size)
{
    const float* node_emb = (const float*)d_in[0];
    const float* ew       = (const float*)d_in[1];
    const int*   src      = (const int*)d_in[2];
    const int*   dst      = (const int*)d_in[3];
    const float* W        = (const float*)d_in[4];
    float*       out      = (float*)d_out;

    const int n_nodes = in_sizes[0] / DIM;
    const int n_edges = in_sizes[1];

    // out is poisoned; scatter accumulates, so zero it first (graph-capturable).
    cudaMemsetAsync(d_out, 0, (size_t)out_size * sizeof(float));

    // 1) T = node_emb @ W^T
    int gemm_blocks = (n_nodes + 127) / 128;
    transform_kernel<<<gemm_blocks, 256>>>(node_emb, W, n_nodes);

    // 2) scatter-add transformed messages into out
    long long warps_needed = n_edges;
    int blocks = (int)((warps_needed * 32 + 255) / 256);
    scatter_kernel<<<blocks, 256>>>(ew, src, dst, out, n_edges);
}

// round 2
// speedup vs baseline: 1.2604x; 1.2604x over previous
#include <cuda_runtime.h>
#include <cstdint>

#define N_NODES_MAX 100000
#define DIM 128

// 51.2 MB scratch for transformed node features
__device__ float g_T[(size_t)N_NODES_MAX * DIM];

// ---------------------------------------------------------------------------
// Kernel 1: T = node_emb @ W^T
// 128x128 tile / block, 256 threads, 8x8 micro-tile (8 CONTIGUOUS rows per
// thread -> A-fragment is 2 vector LDS), BK=8, double-buffered smem (1 sync).
// ---------------------------------------------------------------------------
__global__ __launch_bounds__(256, 2)
void transform_kernel(const float* __restrict__ E, const float* __restrict__ W, int n_rows)
{
    __shared__ float Es[2][8][132];   // Es[buf][kk][r]
    __shared__ float Ws[2][8][132];   // Ws[buf][kk][j] = W[j][k0+kk]

    const int tid  = threadIdx.x;
    const int tx   = tid & 15;        // 16 column groups (cols tx*4, tx*4+64)
    const int ty   = tid >> 4;        // 16 row groups (rows ty*8 .. ty*8+7)
    const int row0 = blockIdx.x * 128;

    // loader mapping: each thread loads one float4 per array per stage
    const int lr = tid >> 1;          // 0..127 : row (E) / out-col j (W)
    const int lk = (tid & 1) * 4;     // 0 or 4 : k offset within stage

    float acc[8][8];
#pragma unroll
    for (int i = 0; i < 8; i++)
#pragma unroll
        for (int j = 0; j < 8; j++) acc[i][j] = 0.f;

    const int erow = row0 + lr;
    const bool erow_ok = (erow < n_rows);

    // prefetch stage 0
    {
        float4 ea = make_float4(0.f, 0.f, 0.f, 0.f);
        if (erow_ok) ea = *reinterpret_cast<const float4*>(&E[(size_t)erow * DIM + lk]);
        float4 wa = *reinterpret_cast<const float4*>(&W[(size_t)lr * DIM + lk]);
        Es[0][lk + 0][lr] = ea.x; Es[0][lk + 1][lr] = ea.y;
        Es[0][lk + 2][lr] = ea.z; Es[0][lk + 3][lr] = ea.w;
        Ws[0][lk + 0][lr] = wa.x; Ws[0][lk + 1][lr] = wa.y;
        Ws[0][lk + 2][lr] = wa.z; Ws[0][lk + 3][lr] = wa.w;
    }
    __syncthreads();

    int buf = 0;
#pragma unroll 1
    for (int k0 = 0; k0 < 128; k0 += 8) {
        // prefetch next stage into registers
        float4 en = make_float4(0.f, 0.f, 0.f, 0.f);
        float4 wn;
        const bool has_next = (k0 + 8) < 128;
        if (has_next) {
            if (erow_ok)
                en = *reinterpret_cast<const float4*>(&E[(size_t)erow * DIM + k0 + 8 + lk]);
            wn = *reinterpret_cast<const float4*>(&W[(size_t)lr * DIM + k0 + 8 + lk]);
        }

        // compute current stage
#pragma unroll
        for (int kk = 0; kk < 8; kk++) {
            float4 a0 = *reinterpret_cast<const float4*>(&Es[buf][kk][ty * 8]);
            float4 a1 = *reinterpret_cast<const float4*>(&Es[buf][kk][ty * 8 + 4]);
            float4 b0 = *reinterpret_cast<const float4*>(&Ws[buf][kk][tx * 4]);
            float4 b1 = *reinterpret_cast<const float4*>(&Ws[buf][kk][tx * 4 + 64]);
            float a[8] = {a0.x, a0.y, a0.z, a0.w, a1.x, a1.y, a1.z, a1.w};
#pragma unroll
            for (int i = 0; i < 8; i++) {
                acc[i][0] += a[i] * b0.x;
                acc[i][1] += a[i] * b0.y;
                acc[i][2] += a[i] * b0.z;
                acc[i][3] += a[i] * b0.w;
                acc[i][4] += a[i] * b1.x;
                acc[i][5] += a[i] * b1.y;
                acc[i][6] += a[i] * b1.z;
                acc[i][7] += a[i] * b1.w;
            }
        }

        // store prefetched stage to the other buffer (safe: it was last read
        // before the previous __syncthreads)
        if (has_next) {
            int nb = buf ^ 1;
            Es[nb][lk + 0][lr] = en.x; Es[nb][lk + 1][lr] = en.y;
            Es[nb][lk + 2][lr] = en.z; Es[nb][lk + 3][lr] = en.w;
            Ws[nb][lk + 0][lr] = wn.x; Ws[nb][lk + 1][lr] = wn.y;
            Ws[nb][lk + 2][lr] = wn.z; Ws[nb][lk + 3][lr] = wn.w;
            buf = nb;
        }
        __syncthreads();
    }

#pragma unroll
    for (int i = 0; i < 8; i++) {
        int row = row0 + ty * 8 + i;
        if (row < n_rows) {
            float4 v0 = make_float4(acc[i][0], acc[i][1], acc[i][2], acc[i][3]);
            float4 v1 = make_float4(acc[i][4], acc[i][5], acc[i][6], acc[i][7]);
            *reinterpret_cast<float4*>(&g_T[(size_t)row * DIM + tx * 4])      = v0;
            *reinterpret_cast<float4*>(&g_T[(size_t)row * DIM + tx * 4 + 64]) = v1;
        }
    }
}

// ---------------------------------------------------------------------------
// Kernel 2: out[dst[e]] += T[src[e]] * w[e]
// 4 edges per warp: broadcast int4/float4 metadata loads, then 4 independent
// T-row gathers in flight (MLP=4) before 4 red.global.add.v4.f32.
// ---------------------------------------------------------------------------
#define EPW 4

__global__ __launch_bounds__(256)
void scatter_kernel(const float* __restrict__ ew,
                    const int*   __restrict__ src,
                    const int*   __restrict__ dst,
                    float*       __restrict__ out,
                    int n_edges)
{
    int warp = (int)((blockIdx.x * (unsigned)blockDim.x + threadIdx.x) >> 5);
    int lane = threadIdx.x & 31;
    int e0 = warp * EPW;
    if (e0 >= n_edges) return;

    if (e0 + EPW <= n_edges) {
        // broadcast vector loads (all lanes same address -> L1 broadcast)
        int4   s4 = *reinterpret_cast<const int4*>(src + e0);
        int4   d4 = *reinterpret_cast<const int4*>(dst + e0);
        float4 w4 = *reinterpret_cast<const float4*>(ew + e0);
        int   s[EPW] = {s4.x, s4.y, s4.z, s4.w};
        int   d[EPW] = {d4.x, d4.y, d4.z, d4.w};
        float w[EPW] = {w4.x, w4.y, w4.z, w4.w};

        float4 v[EPW];
#pragma unroll
        for (int k = 0; k < EPW; k++)
            v[k] = *reinterpret_cast<const float4*>(&g_T[(size_t)s[k] * DIM + lane * 4]);

#pragma unroll
        for (int k = 0; k < EPW; k++) {
            float4 t = v[k];
            t.x *= w[k]; t.y *= w[k]; t.z *= w[k]; t.w *= w[k];
            float* o = out + (size_t)d[k] * DIM + lane * 4;
            asm volatile("red.global.add.v4.f32 [%0], {%1, %2, %3, %4};"
                         :: "l"(o), "f"(t.x), "f"(t.y), "f"(t.z), "f"(t.w)
                         : "memory");
        }
    } else {
        for (int e = e0; e < n_edges; e++) {
            int   s = __ldg(&src[e]);
            int   d = __ldg(&dst[e]);
            float w = __ldg(&ew[e]);
            float4 t = *reinterpret_cast<const float4*>(&g_T[(size_t)s * DIM + lane * 4]);
            t.x *= w; t.y *= w; t.z *= w; t.w *= w;
            float* o = out + (size_t)d * DIM + lane * 4;
            asm volatile("red.global.add.v4.f32 [%0], {%1, %2, %3, %4};"
                         :: "l"(o), "f"(t.x), "f"(t.y), "f"(t.z), "f"(t.w)
                         : "memory");
        }
    }
}

// ---------------------------------------------------------------------------
extern "C" void kernel_launch(void* const* d_in, const int* in_sizes, int n_in,
                              void* d_out, int out_size)
{
    const float* node_emb = (const float*)d_in[0];
    const float* ew       = (const float*)d_in[1];
    const int*   src      = (const int*)d_in[2];
    const int*   dst      = (const int*)d_in[3];
    const float* W        = (const float*)d_in[4];
    float*       out      = (float*)d_out;

    const int n_nodes = in_sizes[0] / DIM;
    const int n_edges = in_sizes[1];

    cudaMemsetAsync(d_out, 0, (size_t)out_size * sizeof(float));

    int gemm_blocks = (n_nodes + 127) / 128;
    transform_kernel<<<gemm_blocks, 256>>>(node_emb, W, n_nodes);

    int warps_needed = (n_edges + EPW - 1) / EPW;
    int blocks = (warps_needed * 32 + 255) / 256;
    scatter_kernel<<<blocks, 256>>>(ew, src, dst, out, n_edges);
}

// round 3
// speedup vs baseline: 1.4847x; 1.1780x over previous
#include <cuda_runtime.h>
#include <cstdint>

#define N_NODES_MAX 100000
#define EDGE_MAX    1600000
#define DIM 128

// scratch (allocation-free rule: __device__ globals)
__device__ float    g_T[(size_t)N_NODES_MAX * DIM];   // transformed features
__device__ unsigned g_cnt[N_NODES_MAX];               // per-dst degree
__device__ unsigned g_off[N_NODES_MAX];               // exclusive scan of degree
__device__ unsigned g_cur[N_NODES_MAX];               // bucket cursors (mutated)
__device__ unsigned g_bsum[256];                      // block sums for scan
__device__ uint2    g_sorted[EDGE_MAX];               // (src, weight_bits) sorted by dst

// ---------------------------------------------------------------------------
// Kernel 1: T = node_emb @ W^T   (unchanged from R2)
// ---------------------------------------------------------------------------
__global__ __launch_bounds__(256, 2)
void transform_kernel(const float* __restrict__ E, const float* __restrict__ W, int n_rows)
{
    __shared__ float Es[2][8][132];
    __shared__ float Ws[2][8][132];

    const int tid  = threadIdx.x;
    const int tx   = tid & 15;
    const int ty   = tid >> 4;
    const int row0 = blockIdx.x * 128;
    const int lr = tid >> 1;
    const int lk = (tid & 1) * 4;

    float acc[8][8];
#pragma unroll
    for (int i = 0; i < 8; i++)
#pragma unroll
        for (int j = 0; j < 8; j++) acc[i][j] = 0.f;

    const int erow = row0 + lr;
    const bool erow_ok = (erow < n_rows);

    {
        float4 ea = make_float4(0.f, 0.f, 0.f, 0.f);
        if (erow_ok) ea = *reinterpret_cast<const float4*>(&E[(size_t)erow * DIM + lk]);
        float4 wa = *reinterpret_cast<const float4*>(&W[(size_t)lr * DIM + lk]);
        Es[0][lk + 0][lr] = ea.x; Es[0][lk + 1][lr] = ea.y;
        Es[0][lk + 2][lr] = ea.z; Es[0][lk + 3][lr] = ea.w;
        Ws[0][lk + 0][lr] = wa.x; Ws[0][lk + 1][lr] = wa.y;
        Ws[0][lk + 2][lr] = wa.z; Ws[0][lk + 3][lr] = wa.w;
    }
    __syncthreads();

    int buf = 0;
#pragma unroll 1
    for (int k0 = 0; k0 < 128; k0 += 8) {
        float4 en = make_float4(0.f, 0.f, 0.f, 0.f);
        float4 wn;
        const bool has_next = (k0 + 8) < 128;
        if (has_next) {
            if (erow_ok)
                en = *reinterpret_cast<const float4*>(&E[(size_t)erow * DIM + k0 + 8 + lk]);
            wn = *reinterpret_cast<const float4*>(&W[(size_t)lr * DIM + k0 + 8 + lk]);
        }

#pragma unroll
        for (int kk = 0; kk < 8; kk++) {
            float4 a0 = *reinterpret_cast<const float4*>(&Es[buf][kk][ty * 8]);
            float4 a1 = *reinterpret_cast<const float4*>(&Es[buf][kk][ty * 8 + 4]);
            float4 b0 = *reinterpret_cast<const float4*>(&Ws[buf][kk][tx * 4]);
            float4 b1 = *reinterpret_cast<const float4*>(&Ws[buf][kk][tx * 4 + 64]);
            float a[8] = {a0.x, a0.y, a0.z, a0.w, a1.x, a1.y, a1.z, a1.w};
#pragma unroll
            for (int i = 0; i < 8; i++) {
                acc[i][0] += a[i] * b0.x;
                acc[i][1] += a[i] * b0.y;
                acc[i][2] += a[i] * b0.z;
                acc[i][3] += a[i] * b0.w;
                acc[i][4] += a[i] * b1.x;
                acc[i][5] += a[i] * b1.y;
                acc[i][6] += a[i] * b1.z;
                acc[i][7] += a[i] * b1.w;
            }
        }

        if (has_next) {
            int nb = buf ^ 1;
            Es[nb][lk + 0][lr] = en.x; Es[nb][lk + 1][lr] = en.y;
            Es[nb][lk + 2][lr] = en.z; Es[nb][lk + 3][lr] = en.w;
            Ws[nb][lk + 0][lr] = wn.x; Ws[nb][lk + 1][lr] = wn.y;
            Ws[nb][lk + 2][lr] = wn.z; Ws[nb][lk + 3][lr] = wn.w;
            buf = nb;
        }
        __syncthreads();
    }

#pragma unroll
    for (int i = 0; i < 8; i++) {
        int row = row0 + ty * 8 + i;
        if (row < n_rows) {
            float4 v0 = make_float4(acc[i][0], acc[i][1], acc[i][2], acc[i][3]);
            float4 v1 = make_float4(acc[i][4], acc[i][5], acc[i][6], acc[i][7]);
            *reinterpret_cast<float4*>(&g_T[(size_t)row * DIM + tx * 4])      = v0;
            *reinterpret_cast<float4*>(&g_T[(size_t)row * DIM + tx * 4 + 64]) = v1;
        }
    }
}

// ---------------------------------------------------------------------------
// Sort pipeline: histogram -> scan -> bucket scatter
// ---------------------------------------------------------------------------
__global__ void hist_kernel(const int* __restrict__ dst, int n_edges)
{
    int e = blockIdx.x * blockDim.x + threadIdx.x;
    if (e < n_edges) atomicAdd(&g_cnt[dst[e]], 1u);
}

// chunk-wise exclusive scan (1024 elems / block)
__global__ __launch_bounds__(1024)
void scan1_kernel(int n)
{
    __shared__ unsigned s[1024];
    int i = blockIdx.x * 1024 + threadIdx.x;
    unsigned v = (i < n) ? g_cnt[i] : 0u;
    s[threadIdx.x] = v;
    __syncthreads();
#pragma unroll
    for (int d = 1; d < 1024; d <<= 1) {
        unsigned t = (threadIdx.x >= d) ? s[threadIdx.x - d] : 0u;
        __syncthreads();
        s[threadIdx.x] += t;
        __syncthreads();
    }
    unsigned incl = s[threadIdx.x];
    if (i < n) g_off[i] = incl - v;          // exclusive within chunk
    if (threadIdx.x == 1023) g_bsum[blockIdx.x] = incl;
}

__global__ void scan2_kernel(int nblocks)
{
    if (threadIdx.x == 0) {
        unsigned run = 0;
        for (int b = 0; b < nblocks; b++) {
            unsigned t = g_bsum[b];
            g_bsum[b] = run;
            run += t;
        }
    }
}

__global__ __launch_bounds__(1024)
void scan3_kernel(int n)
{
    int i = blockIdx.x * 1024 + threadIdx.x;
    if (i < n) {
        unsigned o = g_off[i] + g_bsum[i >> 10];
        g_off[i] = o;
        g_cur[i] = o;
    }
}

__global__ void bucket_kernel(const int* __restrict__ src,
                              const int* __restrict__ dst,
                              const float* __restrict__ ew,
                              int n_edges)
{
    int e = blockIdx.x * blockDim.x + threadIdx.x;
    if (e < n_edges) {
        int d = dst[e];
        unsigned pos = atomicAdd(&g_cur[d], 1u);
        g_sorted[pos] = make_uint2((unsigned)src[e], __float_as_uint(ew[e]));
    }
}

// ---------------------------------------------------------------------------
// Aggregation: one warp per dst node; contiguous edge bucket; register
// accumulation; single plain STG.128 per lane. No atomics, no memset needed.
// ---------------------------------------------------------------------------
__global__ __launch_bounds__(256)
void agg_kernel(float* __restrict__ out, int n_nodes, int n_edges)
{
    int node = (int)((blockIdx.x * (unsigned)blockDim.x + threadIdx.x) >> 5);
    int lane = threadIdx.x & 31;
    if (node >= n_nodes) return;

    unsigned start = g_off[node];
    unsigned end   = (node + 1 < n_nodes) ? g_off[node + 1] : (unsigned)n_edges;

    float4 a0 = make_float4(0.f, 0.f, 0.f, 0.f);
    float4 a1 = a0, a2 = a0, a3 = a0;

    unsigned e = start;
    for (; e + 4 <= end; e += 4) {
        // broadcast loads (all lanes same address)
        uint2 p0 = g_sorted[e + 0];
        uint2 p1 = g_sorted[e + 1];
        uint2 p2 = g_sorted[e + 2];
        uint2 p3 = g_sorted[e + 3];
        float4 v0 = *reinterpret_cast<const float4*>(&g_T[(size_t)p0.x * DIM + lane * 4]);
        float4 v1 = *reinterpret_cast<const float4*>(&g_T[(size_t)p1.x * DIM + lane * 4]);
        float4 v2 = *reinterpret_cast<const float4*>(&g_T[(size_t)p2.x * DIM + lane * 4]);
        float4 v3 = *reinterpret_cast<const float4*>(&g_T[(size_t)p3.x * DIM + lane * 4]);
        float w0 = __uint_as_float(p0.y), w1 = __uint_as_float(p1.y);
        float w2 = __uint_as_float(p2.y), w3 = __uint_as_float(p3.y);
        a0.x += v0.x * w0; a0.y += v0.y * w0; a0.z += v0.z * w0; a0.w += v0.w * w0;
        a1.x += v1.x * w1; a1.y += v1.y * w1; a1.z += v1.z * w1; a1.w += v1.w * w1;
        a2.x += v2.x * w2; a2.y += v2.y * w2; a2.z += v2.z * w2; a2.w += v2.w * w2;
        a3.x += v3.x * w3; a3.y += v3.y * w3; a3.z += v3.z * w3; a3.w += v3.w * w3;
    }
    for (; e < end; e++) {
        uint2 p = g_sorted[e];
        float4 v = *reinterpret_cast<const float4*>(&g_T[(size_t)p.x * DIM + lane * 4]);
        float w = __uint_as_float(p.y);
        a0.x += v.x * w; a0.y += v.y * w; a0.z += v.z * w; a0.w += v.w * w;
    }

    float4 r;
    r.x = (a0.x + a1.x) + (a2.x + a3.x);
    r.y = (a0.y + a1.y) + (a2.y + a3.y);
    r.z = (a0.z + a1.z) + (a2.z + a3.z);
    r.w = (a0.w + a1.w) + (a2.w + a3.w);
    *reinterpret_cast<float4*>(&out[(size_t)node * DIM + lane * 4]) = r;
}

// ---------------------------------------------------------------------------
extern "C" void kernel_launch(void* const* d_in, const int* in_sizes, int n_in,
                              void* d_out, int out_size)
{
    const float* node_emb = (const float*)d_in[0];
    const float* ew       = (const float*)d_in[1];
    const int*   src      = (const int*)d_in[2];
    const int*   dst      = (const int*)d_in[3];
    const float* W        = (const float*)d_in[4];
    float*       out      = (float*)d_out;

    const int n_nodes = in_sizes[0] / DIM;
    const int n_edges = in_sizes[1];

    // zero the histogram (device symbol, graph-capturable memset)
    void* cnt_ptr = nullptr;
    cudaGetSymbolAddress(&cnt_ptr, g_cnt);
    cudaMemsetAsync(cnt_ptr, 0, (size_t)n_nodes * sizeof(unsigned));

    // sort pipeline
    int eb = (n_edges + 255) / 256;
    hist_kernel<<<eb, 256>>>(dst, n_edges);
    int nchunks = (n_nodes + 1023) / 1024;
    scan1_kernel<<<nchunks, 1024>>>(n_nodes);
    scan2_kernel<<<1, 32>>>(nchunks);
    scan3_kernel<<<nchunks, 1024>>>(n_nodes);
    bucket_kernel<<<eb, 256>>>(src, dst, ew, n_edges);

    // GEMM (independent of sort pipeline ordering; must precede agg)
    int gemm_blocks = (n_nodes + 127) / 128;
    transform_kernel<<<gemm_blocks, 256>>>(node_emb, W, n_nodes);

    // aggregation
    int warps = n_nodes;
    int ab = (warps * 32 + 255) / 256;
    agg_kernel<<<ab, 256>>>(out, n_nodes, n_edges);
}

// round 5
// speedup vs baseline: 1.6743x; 1.1277x over previous
#include <cuda_runtime.h>
#include <cuda_fp16.h>
#include <cstdint>
#include <cstring>

#define N_NODES_MAX 100000
#define EDGE_MAX    1600000
#define DIM 128

// bit-cast helpers (fold to register moves)
__device__ __forceinline__ unsigned h2_to_u32(__half2 h) {
    unsigned u; memcpy(&u, &h, 4); return u;
}
__device__ __forceinline__ __half2 u32_to_h2(unsigned u) {
    __half2 h; memcpy(&h, &u, 4); return h;
}

// scratch (allocation-free rule: __device__ globals)
__device__ __half   g_Th[(size_t)N_NODES_MAX * DIM];  // transformed features (fp16)
__device__ unsigned g_cnt[N_NODES_MAX];               // per-dst degree
__device__ unsigned g_off[N_NODES_MAX];               // exclusive scan of degree
__device__ unsigned g_cur[N_NODES_MAX];               // bucket cursors (mutated)
__device__ unsigned g_bsum[256];                      // block sums for scan
__device__ uint2    g_sorted[EDGE_MAX];               // (src, weight_bits) sorted by dst

// ---------------------------------------------------------------------------
// Kernel 1: T = node_emb @ W^T  (f32 compute, fp16 store)
// ---------------------------------------------------------------------------
__global__ __launch_bounds__(256, 2)
void transform_kernel(const float* __restrict__ E, const float* __restrict__ W, int n_rows)
{
    __shared__ float Es[2][8][132];
    __shared__ float Ws[2][8][132];

    const int tid  = threadIdx.x;
    const int tx   = tid & 15;
    const int ty   = tid >> 4;
    const int row0 = blockIdx.x * 128;
    const int lr = tid >> 1;
    const int lk = (tid & 1) * 4;

    float acc[8][8];
#pragma unroll
    for (int i = 0; i < 8; i++)
#pragma unroll
        for (int j = 0; j < 8; j++) acc[i][j] = 0.f;

    const int erow = row0 + lr;
    const bool erow_ok = (erow < n_rows);

    {
        float4 ea = make_float4(0.f, 0.f, 0.f, 0.f);
        if (erow_ok) ea = *reinterpret_cast<const float4*>(&E[(size_t)erow * DIM + lk]);
        float4 wa = *reinterpret_cast<const float4*>(&W[(size_t)lr * DIM + lk]);
        Es[0][lk + 0][lr] = ea.x; Es[0][lk + 1][lr] = ea.y;
        Es[0][lk + 2][lr] = ea.z; Es[0][lk + 3][lr] = ea.w;
        Ws[0][lk + 0][lr] = wa.x; Ws[0][lk + 1][lr] = wa.y;
        Ws[0][lk + 2][lr] = wa.z; Ws[0][lk + 3][lr] = wa.w;
    }
    __syncthreads();

    int buf = 0;
#pragma unroll 1
    for (int k0 = 0; k0 < 128; k0 += 8) {
        float4 en = make_float4(0.f, 0.f, 0.f, 0.f);
        float4 wn;
        const bool has_next = (k0 + 8) < 128;
        if (has_next) {
            if (erow_ok)
                en = *reinterpret_cast<const float4*>(&E[(size_t)erow * DIM + k0 + 8 + lk]);
            wn = *reinterpret_cast<const float4*>(&W[(size_t)lr * DIM + k0 + 8 + lk]);
        }

#pragma unroll
        for (int kk = 0; kk < 8; kk++) {
            float4 a0 = *reinterpret_cast<const float4*>(&Es[buf][kk][ty * 8]);
            float4 a1 = *reinterpret_cast<const float4*>(&Es[buf][kk][ty * 8 + 4]);
            float4 b0 = *reinterpret_cast<const float4*>(&Ws[buf][kk][tx * 4]);
            float4 b1 = *reinterpret_cast<const float4*>(&Ws[buf][kk][tx * 4 + 64]);
            float a[8] = {a0.x, a0.y, a0.z, a0.w, a1.x, a1.y, a1.z, a1.w};
#pragma unroll
            for (int i = 0; i < 8; i++) {
                acc[i][0] += a[i] * b0.x;
                acc[i][1] += a[i] * b0.y;
                acc[i][2] += a[i] * b0.z;
                acc[i][3] += a[i] * b0.w;
                acc[i][4] += a[i] * b1.x;
                acc[i][5] += a[i] * b1.y;
                acc[i][6] += a[i] * b1.z;
                acc[i][7] += a[i] * b1.w;
            }
        }

        if (has_next) {
            int nb = buf ^ 1;
            Es[nb][lk + 0][lr] = en.x; Es[nb][lk + 1][lr] = en.y;
            Es[nb][lk + 2][lr] = en.z; Es[nb][lk + 3][lr] = en.w;
            Ws[nb][lk + 0][lr] = wn.x; Ws[nb][lk + 1][lr] = wn.y;
            Ws[nb][lk + 2][lr] = wn.z; Ws[nb][lk + 3][lr] = wn.w;
            buf = nb;
        }
        __syncthreads();
    }

#pragma unroll
    for (int i = 0; i < 8; i++) {
        int row = row0 + ty * 8 + i;
        if (row < n_rows) {
            uint2 u0 = make_uint2(h2_to_u32(__floats2half2_rn(acc[i][0], acc[i][1])),
                                  h2_to_u32(__floats2half2_rn(acc[i][2], acc[i][3])));
            uint2 u1 = make_uint2(h2_to_u32(__floats2half2_rn(acc[i][4], acc[i][5])),
                                  h2_to_u32(__floats2half2_rn(acc[i][6], acc[i][7])));
            *reinterpret_cast<uint2*>(&g_Th[(size_t)row * DIM + tx * 4])      = u0;
            *reinterpret_cast<uint2*>(&g_Th[(size_t)row * DIM + tx * 4 + 64]) = u1;
        }
    }
}

// ---------------------------------------------------------------------------
// Sort pipeline: histogram -> scan -> bucket scatter
// ---------------------------------------------------------------------------
__global__ void hist_kernel(const int* __restrict__ dst, int n_edges)
{
    int e = blockIdx.x * blockDim.x + threadIdx.x;
    if (e < n_edges) atomicAdd(&g_cnt[dst[e]], 1u);
}

__global__ __launch_bounds__(1024)
void scan1_kernel(int n)
{
    __shared__ unsigned s[1024];
    int i = blockIdx.x * 1024 + threadIdx.x;
    unsigned v = (i < n) ? g_cnt[i] : 0u;
    s[threadIdx.x] = v;
    __syncthreads();
#pragma unroll
    for (int d = 1; d < 1024; d <<= 1) {
        unsigned t = (threadIdx.x >= d) ? s[threadIdx.x - d] : 0u;
        __syncthreads();
        s[threadIdx.x] += t;
        __syncthreads();
    }
    unsigned incl = s[threadIdx.x];
    if (i < n) g_off[i] = incl - v;
    if (threadIdx.x == 1023) g_bsum[blockIdx.x] = incl;
}

__global__ void scan2_kernel(int nblocks)
{
    if (threadIdx.x == 0) {
        unsigned run = 0;
        for (int b = 0; b < nblocks; b++) {
            unsigned t = g_bsum[b];
            g_bsum[b] = run;
            run += t;
        }
    }
}

__global__ __launch_bounds__(1024)
void scan3_kernel(int n)
{
    int i = blockIdx.x * 1024 + threadIdx.x;
    if (i < n) {
        unsigned o = g_off[i] + g_bsum[i >> 10];
        g_off[i] = o;
        g_cur[i] = o;
    }
}

__global__ void bucket_kernel(const int* __restrict__ src,
                              const int* __restrict__ dst,
                              const float* __restrict__ ew,
                              int n_edges)
{
    int e = blockIdx.x * blockDim.x + threadIdx.x;
    if (e < n_edges) {
        int d = dst[e];
        unsigned pos = atomicAdd(&g_cur[d], 1u);
        g_sorted[pos] = make_uint2((unsigned)src[e], __float_as_uint(ew[e]));
    }
}

// ---------------------------------------------------------------------------
// Aggregation: one warp per dst node; fp16 gather (uint2/lane), f32 accumulate,
// single STG.128 per lane. No atomics.
// ---------------------------------------------------------------------------
__global__ __launch_bounds__(256)
void agg_kernel(float* __restrict__ out, int n_nodes, int n_edges)
{
    int node = (int)((blockIdx.x * (unsigned)blockDim.x + threadIdx.x) >> 5);
    int lane = threadIdx.x & 31;
    if (node >= n_nodes) return;

    unsigned start = g_off[node];
    unsigned end   = (node + 1 < n_nodes) ? g_off[node + 1] : (unsigned)n_edges;

    float4 a0 = make_float4(0.f, 0.f, 0.f, 0.f);
    float4 a1 = a0, a2 = a0, a3 = a0;

    unsigned e = start;
    for (; e + 4 <= end; e += 4) {
        uint2 p0 = g_sorted[e + 0];
        uint2 p1 = g_sorted[e + 1];
        uint2 p2 = g_sorted[e + 2];
        uint2 p3 = g_sorted[e + 3];
        uint2 h0 = *reinterpret_cast<const uint2*>(&g_Th[(size_t)p0.x * DIM + lane * 4]);
        uint2 h1 = *reinterpret_cast<const uint2*>(&g_Th[(size_t)p1.x * DIM + lane * 4]);
        uint2 h2 = *reinterpret_cast<const uint2*>(&g_Th[(size_t)p2.x * DIM + lane * 4]);
        uint2 h3 = *reinterpret_cast<const uint2*>(&g_Th[(size_t)p3.x * DIM + lane * 4]);
        float w0 = __uint_as_float(p0.y), w1 = __uint_as_float(p1.y);
        float w2 = __uint_as_float(p2.y), w3 = __uint_as_float(p3.y);
        float2 v0a = __half22float2(u32_to_h2(h0.x));
        float2 v0b = __half22float2(u32_to_h2(h0.y));
        float2 v1a = __half22float2(u32_to_h2(h1.x));
        float2 v1b = __half22float2(u32_to_h2(h1.y));
        float2 v2a = __half22float2(u32_to_h2(h2.x));
        float2 v2b = __half22float2(u32_to_h2(h2.y));
        float2 v3a = __half22float2(u32_to_h2(h3.x));
        float2 v3b = __half22float2(u32_to_h2(h3.y));
        a0.x += v0a.x * w0; a0.y += v0a.y * w0; a0.z += v0b.x * w0; a0.w += v0b.y * w0;
        a1.x += v1a.x * w1; a1.y += v1a.y * w1; a1.z += v1b.x * w1; a1.w += v1b.y * w1;
        a2.x += v2a.x * w2; a2.y += v2a.y * w2; a2.z += v2b.x * w2; a2.w += v2b.y * w2;
        a3.x += v3a.x * w3; a3.y += v3a.y * w3; a3.z += v3b.x * w3; a3.w += v3b.y * w3;
    }
    for (; e < end; e++) {
        uint2 p = g_sorted[e];
        uint2 h = *reinterpret_cast<const uint2*>(&g_Th[(size_t)p.x * DIM + lane * 4]);
        float w = __uint_as_float(p.y);
        float2 va = __half22float2(u32_to_h2(h.x));
        float2 vb = __half22float2(u32_to_h2(h.y));
        a0.x += va.x * w; a0.y += va.y * w; a0.z += vb.x * w; a0.w += vb.y * w;
    }

    float4 r;
    r.x = (a0.x + a1.x) + (a2.x + a3.x);
    r.y = (a0.y + a1.y) + (a2.y + a3.y);
    r.z = (a0.z + a1.z) + (a2.z + a3.z);
    r.w = (a0.w + a1.w) + (a2.w + a3.w);
    *reinterpret_cast<float4*>(&out[(size_t)node * DIM + lane * 4]) = r;
}

// ---------------------------------------------------------------------------
extern "C" void kernel_launch(void* const* d_in, const int* in_sizes, int n_in,
                              void* d_out, int out_size)
{
    const float* node_emb = (const float*)d_in[0];
    const float* ew       = (const float*)d_in[1];
    const int*   src      = (const int*)d_in[2];
    const int*   dst      = (const int*)d_in[3];
    const float* W        = (const float*)d_in[4];
    float*       out      = (float*)d_out;

    const int n_nodes = in_sizes[0] / DIM;
    const int n_edges = in_sizes[1];

    void* cnt_ptr = nullptr;
    cudaGetSymbolAddress(&cnt_ptr, g_cnt);
    cudaMemsetAsync(cnt_ptr, 0, (size_t)n_nodes * sizeof(unsigned));

    int eb = (n_edges + 255) / 256;
    hist_kernel<<<eb, 256>>>(dst, n_edges);
    int nchunks = (n_nodes + 1023) / 1024;
    scan1_kernel<<<nchunks, 1024>>>(n_nodes);
    scan2_kernel<<<1, 32>>>(nchunks);
    scan3_kernel<<<nchunks, 1024>>>(n_nodes);
    bucket_kernel<<<eb, 256>>>(src, dst, ew, n_edges);

    int gemm_blocks = (n_nodes + 127) / 128;
    transform_kernel<<<gemm_blocks, 256>>>(node_emb, W, n_nodes);

    int warps = n_nodes;
    int ab = (warps * 32 + 255) / 256;
    agg_kernel<<<ab, 256>>>(out, n_nodes, n_edges);
}

// round 6
// speedup vs baseline: 2.3257x; 1.3891x over previous
#include <cuda_runtime.h>
#include <cuda_fp16.h>
#include <cstdint>
#include <cstring>

#define N_NODES_MAX 100000
#define EDGE_MAX    1600000
#define DIM 128

// bit-cast helpers (fold to register moves)
__device__ __forceinline__ unsigned h2_to_u32(__half2 h) {
    unsigned u; memcpy(&u, &h, 4); return u;
}
__device__ __forceinline__ __half2 u32_to_h2(unsigned u) {
    __half2 h; memcpy(&h, &u, 4); return h;
}
__device__ __forceinline__ uint32_t smem_u32(const void* p) {
    uint32_t a;
    asm("{ .reg .u64 t; cvta.to.shared.u64 t, %1; cvt.u32.u64 %0, t; }" : "=r"(a) : "l"(p));
    return a;
}

#define LDSM_X4(r0, r1, r2, r3, addr)                                         \
    asm volatile("ldmatrix.sync.aligned.m8n8.x4.shared.b16 {%0,%1,%2,%3}, [%4];" \
                 : "=r"(r0), "=r"(r1), "=r"(r2), "=r"(r3) : "r"(addr))

#define MMA16816(c, a0, a1, a2, a3, b0, b1)                                   \
    asm volatile("mma.sync.aligned.m16n8k16.row.col.f32.f16.f16.f32 "         \
                 "{%0,%1,%2,%3}, {%4,%5,%6,%7}, {%8,%9}, {%0,%1,%2,%3};"      \
                 : "+f"(c[0]), "+f"(c[1]), "+f"(c[2]), "+f"(c[3])             \
                 : "r"(a0), "r"(a1), "r"(a2), "r"(a3), "r"(b0), "r"(b1))

// scratch (allocation-free rule: __device__ globals)
__device__ __half   g_Th[(size_t)N_NODES_MAX * DIM];  // transformed features (fp16)
__device__ unsigned g_cnt[N_NODES_MAX];
__device__ unsigned g_off[N_NODES_MAX];
__device__ unsigned g_cur[N_NODES_MAX];
__device__ unsigned g_bsum[256];
__device__ uint2    g_sorted[EDGE_MAX];               // (src, weight_bits) sorted by dst

// ---------------------------------------------------------------------------
// Kernel 1: T = node_emb @ W^T via HMMA (fp16 in, f32 acc, fp16 out).
// 128-row tile / block, 8 warps; warp w owns rows w*16..w*16+15, all 128 cols.
// Padded smem stride 136 halves -> conflict-free ldmatrix phases.
// B fragments load straight from W rows: row.col B-col-major == W[n][k].
// ---------------------------------------------------------------------------
#define SMS 136  // smem row stride in halves

__global__ __launch_bounds__(256, 2)
void transform_mma_kernel(const float* __restrict__ E, const float* __restrict__ W, int n_rows)
{
    extern __shared__ __half sm[];
    __half* As = sm;               // [128][SMS]
    __half* Ws = sm + 128 * SMS;   // [128][SMS]

    const int tid  = threadIdx.x;
    const int row0 = blockIdx.x * 128;

    // cooperative load+convert: E tile (zero-padded past n_rows) and full W
#pragma unroll
    for (int i = 0; i < 16; i++) {
        int idx = tid + i * 256;       // 0..4095
        int r   = idx >> 5;            // 0..127
        int c4  = idx & 31;            // float4 column index
        float4 v = make_float4(0.f, 0.f, 0.f, 0.f);
        int er = row0 + r;
        if (er < n_rows) v = *reinterpret_cast<const float4*>(&E[(size_t)er * DIM + c4 * 4]);
        uint2 ue = make_uint2(h2_to_u32(__floats2half2_rn(v.x, v.y)),
                              h2_to_u32(__floats2half2_rn(v.z, v.w)));
        *reinterpret_cast<uint2*>(&As[r * SMS + c4 * 4]) = ue;

        float4 wv = *reinterpret_cast<const float4*>(&W[(size_t)r * DIM + c4 * 4]);
        uint2 uw = make_uint2(h2_to_u32(__floats2half2_rn(wv.x, wv.y)),
                              h2_to_u32(__floats2half2_rn(wv.z, wv.w)));
        *reinterpret_cast<uint2*>(&Ws[r * SMS + c4 * 4]) = uw;
    }
    __syncthreads();

    const int lane = tid & 31;
    const int warp = tid >> 5;
    const int r0   = warp * 16;

    // ldmatrix row pointers
    // A x4: lanes 0-15 -> rows r0+ (lane&15) @ col k0 ; lanes 16-31 -> same rows @ k0+8
    uint32_t a_base = smem_u32(&As[(r0 + (lane & 15)) * SMS + ((lane >> 4) * 8)]);
    // B x4: lanes 0-7: W rows n0..n0+7 @ k0 ; 8-15: same rows @ k0+8 ;
    //       16-23: rows n0+8..15 @ k0 ; 24-31: rows n0+8..15 @ k0+8
    int brow = (lane & 7) + ((lane & 16) ? 8 : 0);
    int bcol = ((lane >> 3) & 1) * 8;
    uint32_t b_base = smem_u32(&Ws[brow * SMS + bcol]);

    float c[16][4];
#pragma unroll
    for (int j = 0; j < 16; j++)
#pragma unroll
        for (int q = 0; q < 4; q++) c[j][q] = 0.f;

#pragma unroll
    for (int k0 = 0; k0 < 128; k0 += 16) {
        uint32_t a0, a1, a2, a3;
        LDSM_X4(a0, a1, a2, a3, a_base + k0 * 2);
#pragma unroll
        for (int np = 0; np < 8; np++) {
            uint32_t b0, b1, b2, b3;
            LDSM_X4(b0, b1, b2, b3, b_base + (np * 16 * SMS + k0) * 2);
            MMA16816(c[2 * np],     a0, a1, a2, a3, b0, b1);
            MMA16816(c[2 * np + 1], a0, a1, a2, a3, b2, b3);
        }
    }

    // epilogue: C[g][2t],C[g][2t+1] / C[g+8][...] -> half2 stores
    const int g = lane >> 2, t = lane & 3;
    const int rowA = row0 + r0 + g;
    const int rowB = rowA + 8;
#pragma unroll
    for (int j = 0; j < 16; j++) {
        __half2 h01 = __floats2half2_rn(c[j][0], c[j][1]);
        __half2 h23 = __floats2half2_rn(c[j][2], c[j][3]);
        int col = j * 8 + 2 * t;
        if (rowA < n_rows)
            *reinterpret_cast<__half2*>(&g_Th[(size_t)rowA * DIM + col]) = h01;
        if (rowB < n_rows)
            *reinterpret_cast<__half2*>(&g_Th[(size_t)rowB * DIM + col]) = h23;
    }
}

// ---------------------------------------------------------------------------
// Sort pipeline: histogram -> scan -> bucket scatter (unchanged)
// ---------------------------------------------------------------------------
__global__ void hist_kernel(const int* __restrict__ dst, int n_edges)
{
    int e = blockIdx.x * blockDim.x + threadIdx.x;
    if (e < n_edges) atomicAdd(&g_cnt[dst[e]], 1u);
}

__global__ __launch_bounds__(1024)
void scan1_kernel(int n)
{
    __shared__ unsigned s[1024];
    int i = blockIdx.x * 1024 + threadIdx.x;
    unsigned v = (i < n) ? g_cnt[i] : 0u;
    s[threadIdx.x] = v;
    __syncthreads();
#pragma unroll
    for (int d = 1; d < 1024; d <<= 1) {
        unsigned t = (threadIdx.x >= d) ? s[threadIdx.x - d] : 0u;
        __syncthreads();
        s[threadIdx.x] += t;
        __syncthreads();
    }
    unsigned incl = s[threadIdx.x];
    if (i < n) g_off[i] = incl - v;
    if (threadIdx.x == 1023) g_bsum[blockIdx.x] = incl;
}

__global__ void scan2_kernel(int nblocks)
{
    if (threadIdx.x == 0) {
        unsigned run = 0;
        for (int b = 0; b < nblocks; b++) {
            unsigned t = g_bsum[b];
            g_bsum[b] = run;
            run += t;
        }
    }
}

__global__ __launch_bounds__(1024)
void scan3_kernel(int n)
{
    int i = blockIdx.x * 1024 + threadIdx.x;
    if (i < n) {
        unsigned o = g_off[i] + g_bsum[i >> 10];
        g_off[i] = o;
        g_cur[i] = o;
    }
}

__global__ void bucket_kernel(const int* __restrict__ src,
                              const int* __restrict__ dst,
                              const float* __restrict__ ew,
                              int n_edges)
{
    int e = blockIdx.x * blockDim.x + threadIdx.x;
    if (e < n_edges) {
        int d = dst[e];
        unsigned pos = atomicAdd(&g_cur[d], 1u);
        g_sorted[pos] = make_uint2((unsigned)src[e], __float_as_uint(ew[e]));
    }
}

// ---------------------------------------------------------------------------
// Aggregation: one warp per dst node; fp16 gather, f32 accumulate (unchanged)
// ---------------------------------------------------------------------------
__global__ __launch_bounds__(256)
void agg_kernel(float* __restrict__ out, int n_nodes, int n_edges)
{
    int node = (int)((blockIdx.x * (unsigned)blockDim.x + threadIdx.x) >> 5);
    int lane = threadIdx.x & 31;
    if (node >= n_nodes) return;

    unsigned start = g_off[node];
    unsigned end   = (node + 1 < n_nodes) ? g_off[node + 1] : (unsigned)n_edges;

    float4 a0 = make_float4(0.f, 0.f, 0.f, 0.f);
    float4 a1 = a0, a2 = a0, a3 = a0;

    unsigned e = start;
    for (; e + 4 <= end; e += 4) {
        uint2 p0 = g_sorted[e + 0];
        uint2 p1 = g_sorted[e + 1];
        uint2 p2 = g_sorted[e + 2];
        uint2 p3 = g_sorted[e + 3];
        uint2 h0 = *reinterpret_cast<const uint2*>(&g_Th[(size_t)p0.x * DIM + lane * 4]);
        uint2 h1 = *reinterpret_cast<const uint2*>(&g_Th[(size_t)p1.x * DIM + lane * 4]);
        uint2 h2 = *reinterpret_cast<const uint2*>(&g_Th[(size_t)p2.x * DIM + lane * 4]);
        uint2 h3 = *reinterpret_cast<const uint2*>(&g_Th[(size_t)p3.x * DIM + lane * 4]);
        float w0 = __uint_as_float(p0.y), w1 = __uint_as_float(p1.y);
        float w2 = __uint_as_float(p2.y), w3 = __uint_as_float(p3.y);
        float2 v0a = __half22float2(u32_to_h2(h0.x));
        float2 v0b = __half22float2(u32_to_h2(h0.y));
        float2 v1a = __half22float2(u32_to_h2(h1.x));
        float2 v1b = __half22float2(u32_to_h2(h1.y));
        float2 v2a = __half22float2(u32_to_h2(h2.x));
        float2 v2b = __half22float2(u32_to_h2(h2.y));
        float2 v3a = __half22float2(u32_to_h2(h3.x));
        float2 v3b = __half22float2(u32_to_h2(h3.y));
        a0.x += v0a.x * w0; a0.y += v0a.y * w0; a0.z += v0b.x * w0; a0.w += v0b.y * w0;
        a1.x += v1a.x * w1; a1.y += v1a.y * w1; a1.z += v1b.x * w1; a1.w += v1b.y * w1;
        a2.x += v2a.x * w2; a2.y += v2a.y * w2; a2.z += v2b.x * w2; a2.w += v2b.y * w2;
        a3.x += v3a.x * w3; a3.y += v3a.y * w3; a3.z += v3b.x * w3; a3.w += v3b.y * w3;
    }
    for (; e < end; e++) {
        uint2 p = g_sorted[e];
        uint2 h = *reinterpret_cast<const uint2*>(&g_Th[(size_t)p.x * DIM + lane * 4]);
        float w = __uint_as_float(p.y);
        float2 va = __half22float2(u32_to_h2(h.x));
        float2 vb = __half22float2(u32_to_h2(h.y));
        a0.x += va.x * w; a0.y += va.y * w; a0.z += vb.x * w; a0.w += vb.y * w;
    }

    float4 r;
    r.x = (a0.x + a1.x) + (a2.x + a3.x);
    r.y = (a0.y + a1.y) + (a2.y + a3.y);
    r.z = (a0.z + a1.z) + (a2.z + a3.z);
    r.w = (a0.w + a1.w) + (a2.w + a3.w);
    *reinterpret_cast<float4*>(&out[(size_t)node * DIM + lane * 4]) = r;
}

// ---------------------------------------------------------------------------
extern "C" void kernel_launch(void* const* d_in, const int* in_sizes, int n_in,
                              void* d_out, int out_size)
{
    const float* node_emb = (const float*)d_in[0];
    const float* ew       = (const float*)d_in[1];
    const int*   src      = (const int*)d_in[2];
    const int*   dst      = (const int*)d_in[3];
    const float* W        = (const float*)d_in[4];
    float*       out      = (float*)d_out;

    const int n_nodes = in_sizes[0] / DIM;
    const int n_edges = in_sizes[1];

    void* cnt_ptr = nullptr;
    cudaGetSymbolAddress(&cnt_ptr, g_cnt);
    cudaMemsetAsync(cnt_ptr, 0, (size_t)n_nodes * sizeof(unsigned));

    int eb = (n_edges + 255) / 256;
    hist_kernel<<<eb, 256>>>(dst, n_edges);
    int nchunks = (n_nodes + 1023) / 1024;
    scan1_kernel<<<nchunks, 1024>>>(n_nodes);
    scan2_kernel<<<1, 32>>>(nchunks);
    scan3_kernel<<<nchunks, 1024>>>(n_nodes);
    bucket_kernel<<<eb, 256>>>(src, dst, ew, n_edges);

    // tensor-core transform
    const int smem_bytes = 2 * 128 * SMS * (int)sizeof(__half);  // 69632
    cudaFuncSetAttribute(transform_mma_kernel,
                         cudaFuncAttributeMaxDynamicSharedMemorySize, smem_bytes);
    int gemm_blocks = (n_nodes + 127) / 128;
    transform_mma_kernel<<<gemm_blocks, 256, smem_bytes>>>(node_emb, W, n_nodes);

    int ab = (n_nodes * 32 + 255) / 256;
    agg_kernel<<<ab, 256>>>(out, n_nodes, n_edges);
}

// round 7
// speedup vs baseline: 2.4765x; 1.0648x over previous
#include <cuda_runtime.h>
#include <cuda_fp16.h>
#include <cstdint>
#include <cstring>

#define N_NODES_MAX 100000
#define EDGE_MAX    1600000
#define DIM 128

// bit-cast helpers (fold to register moves)
__device__ __forceinline__ unsigned h2_to_u32(__half2 h) {
    unsigned u; memcpy(&u, &h, 4); return u;
}
__device__ __forceinline__ __half2 u32_to_h2(unsigned u) {
    __half2 h; memcpy(&h, &u, 4); return h;
}
__device__ __forceinline__ uint32_t smem_u32(const void* p) {
    uint32_t a;
    asm("{ .reg .u64 t; cvta.to.shared.u64 t, %1; cvt.u32.u64 %0, t; }" : "=r"(a) : "l"(p));
    return a;
}

#define LDSM_X4(r0, r1, r2, r3, addr)                                         \
    asm volatile("ldmatrix.sync.aligned.m8n8.x4.shared.b16 {%0,%1,%2,%3}, [%4];" \
                 : "=r"(r0), "=r"(r1), "=r"(r2), "=r"(r3) : "r"(addr))

#define MMA16816(c, a0, a1, a2, a3, b0, b1)                                   \
    asm volatile("mma.sync.aligned.m16n8k16.row.col.f32.f16.f16.f32 "         \
                 "{%0,%1,%2,%3}, {%4,%5,%6,%7}, {%8,%9}, {%0,%1,%2,%3};"      \
                 : "+f"(c[0]), "+f"(c[1]), "+f"(c[2]), "+f"(c[3])             \
                 : "r"(a0), "r"(a1), "r"(a2), "r"(a3), "r"(b0), "r"(b1))

// scratch (allocation-free rule: __device__ globals)
__device__ __half   g_Th[(size_t)N_NODES_MAX * DIM];  // transformed features (fp16)
__device__ unsigned g_cnt[N_NODES_MAX];
__device__ unsigned g_off[N_NODES_MAX];
__device__ unsigned g_cur[N_NODES_MAX];
__device__ unsigned g_bsum[256];
__device__ uint2    g_sorted[EDGE_MAX];               // (src, weight_bits) sorted by dst

// ---------------------------------------------------------------------------
// Kernel 1: T = node_emb @ W^T via HMMA (fp16 in, f32 acc, fp16 out).
// ---------------------------------------------------------------------------
#define SMS 136  // smem row stride in halves

__global__ __launch_bounds__(256, 2)
void transform_mma_kernel(const float* __restrict__ E, const float* __restrict__ W, int n_rows)
{
    extern __shared__ __half sm[];
    __half* As = sm;               // [128][SMS]
    __half* Ws = sm + 128 * SMS;   // [128][SMS]

    const int tid  = threadIdx.x;
    const int row0 = blockIdx.x * 128;

#pragma unroll
    for (int i = 0; i < 16; i++) {
        int idx = tid + i * 256;
        int r   = idx >> 5;
        int c4  = idx & 31;
        float4 v = make_float4(0.f, 0.f, 0.f, 0.f);
        int er = row0 + r;
        if (er < n_rows) v = *reinterpret_cast<const float4*>(&E[(size_t)er * DIM + c4 * 4]);
        uint2 ue = make_uint2(h2_to_u32(__floats2half2_rn(v.x, v.y)),
                              h2_to_u32(__floats2half2_rn(v.z, v.w)));
        *reinterpret_cast<uint2*>(&As[r * SMS + c4 * 4]) = ue;

        float4 wv = *reinterpret_cast<const float4*>(&W[(size_t)r * DIM + c4 * 4]);
        uint2 uw = make_uint2(h2_to_u32(__floats2half2_rn(wv.x, wv.y)),
                              h2_to_u32(__floats2half2_rn(wv.z, wv.w)));
        *reinterpret_cast<uint2*>(&Ws[r * SMS + c4 * 4]) = uw;
    }
    __syncthreads();

    const int lane = tid & 31;
    const int warp = tid >> 5;
    const int r0   = warp * 16;

    uint32_t a_base = smem_u32(&As[(r0 + (lane & 15)) * SMS + ((lane >> 4) * 8)]);
    int brow = (lane & 7) + ((lane & 16) ? 8 : 0);
    int bcol = ((lane >> 3) & 1) * 8;
    uint32_t b_base = smem_u32(&Ws[brow * SMS + bcol]);

    float c[16][4];
#pragma unroll
    for (int j = 0; j < 16; j++)
#pragma unroll
        for (int q = 0; q < 4; q++) c[j][q] = 0.f;

#pragma unroll
    for (int k0 = 0; k0 < 128; k0 += 16) {
        uint32_t a0, a1, a2, a3;
        LDSM_X4(a0, a1, a2, a3, a_base + k0 * 2);
#pragma unroll
        for (int np = 0; np < 8; np++) {
            uint32_t b0, b1, b2, b3;
            LDSM_X4(b0, b1, b2, b3, b_base + (np * 16 * SMS + k0) * 2);
            MMA16816(c[2 * np],     a0, a1, a2, a3, b0, b1);
            MMA16816(c[2 * np + 1], a0, a1, a2, a3, b2, b3);
        }
    }

    const int g = lane >> 2, t = lane & 3;
    const int rowA = row0 + r0 + g;
    const int rowB = rowA + 8;
#pragma unroll
    for (int j = 0; j < 16; j++) {
        __half2 h01 = __floats2half2_rn(c[j][0], c[j][1]);
        __half2 h23 = __floats2half2_rn(c[j][2], c[j][3]);
        int col = j * 8 + 2 * t;
        if (rowA < n_rows)
            *reinterpret_cast<__half2*>(&g_Th[(size_t)rowA * DIM + col]) = h01;
        if (rowB < n_rows)
            *reinterpret_cast<__half2*>(&g_Th[(size_t)rowB * DIM + col]) = h23;
    }
}

// ---------------------------------------------------------------------------
// Sort pipeline: histogram -> scan -> bucket scatter
// ---------------------------------------------------------------------------
__global__ void hist_kernel(const int* __restrict__ dst, int n_edges)
{
    int e = blockIdx.x * blockDim.x + threadIdx.x;
    if (e < n_edges) atomicAdd(&g_cnt[dst[e]], 1u);
}

__global__ __launch_bounds__(1024)
void scan1_kernel(int n)
{
    __shared__ unsigned s[1024];
    int i = blockIdx.x * 1024 + threadIdx.x;
    unsigned v = (i < n) ? g_cnt[i] : 0u;
    s[threadIdx.x] = v;
    __syncthreads();
#pragma unroll
    for (int d = 1; d < 1024; d <<= 1) {
        unsigned t = (threadIdx.x >= d) ? s[threadIdx.x - d] : 0u;
        __syncthreads();
        s[threadIdx.x] += t;
        __syncthreads();
    }
    unsigned incl = s[threadIdx.x];
    if (i < n) g_off[i] = incl - v;
    if (threadIdx.x == 1023) g_bsum[blockIdx.x] = incl;
}

__global__ void scan2_kernel(int nblocks)
{
    if (threadIdx.x == 0) {
        unsigned run = 0;
        for (int b = 0; b < nblocks; b++) {
            unsigned t = g_bsum[b];
            g_bsum[b] = run;
            run += t;
        }
    }
}

__global__ __launch_bounds__(1024)
void scan3_kernel(int n)
{
    int i = blockIdx.x * 1024 + threadIdx.x;
    if (i < n) {
        unsigned o = g_off[i] + g_bsum[i >> 10];
        g_off[i] = o;
        g_cur[i] = o;
    }
}

__global__ void bucket_kernel(const int* __restrict__ src,
                              const int* __restrict__ dst,
                              const float* __restrict__ ew,
                              int n_edges)
{
    int e = blockIdx.x * blockDim.x + threadIdx.x;
    if (e < n_edges) {
        int d = dst[e];
        unsigned pos = atomicAdd(&g_cur[d], 1u);
        g_sorted[pos] = make_uint2((unsigned)src[e], __float_as_uint(ew[e]));
    }
}

// ---------------------------------------------------------------------------
// Aggregation: one warp per dst node; fp16 gather, f32 accumulate
// ---------------------------------------------------------------------------
__global__ __launch_bounds__(256)
void agg_kernel(float* __restrict__ out, int n_nodes, int n_edges)
{
    int node = (int)((blockIdx.x * (unsigned)blockDim.x + threadIdx.x) >> 5);
    int lane = threadIdx.x & 31;
    if (node >= n_nodes) return;

    unsigned start = g_off[node];
    unsigned end   = (node + 1 < n_nodes) ? g_off[node + 1] : (unsigned)n_edges;

    float4 a0 = make_float4(0.f, 0.f, 0.f, 0.f);
    float4 a1 = a0, a2 = a0, a3 = a0;

    unsigned e = start;
    for (; e + 4 <= end; e += 4) {
        uint2 p0 = g_sorted[e + 0];
        uint2 p1 = g_sorted[e + 1];
        uint2 p2 = g_sorted[e + 2];
        uint2 p3 = g_sorted[e + 3];
        uint2 h0 = *reinterpret_cast<const uint2*>(&g_Th[(size_t)p0.x * DIM + lane * 4]);
        uint2 h1 = *reinterpret_cast<const uint2*>(&g_Th[(size_t)p1.x * DIM + lane * 4]);
        uint2 h2 = *reinterpret_cast<const uint2*>(&g_Th[(size_t)p2.x * DIM + lane * 4]);
        uint2 h3 = *reinterpret_cast<const uint2*>(&g_Th[(size_t)p3.x * DIM + lane * 4]);
        float w0 = __uint_as_float(p0.y), w1 = __uint_as_float(p1.y);
        float w2 = __uint_as_float(p2.y), w3 = __uint_as_float(p3.y);
        float2 v0a = __half22float2(u32_to_h2(h0.x));
        float2 v0b = __half22float2(u32_to_h2(h0.y));
        float2 v1a = __half22float2(u32_to_h2(h1.x));
        float2 v1b = __half22float2(u32_to_h2(h1.y));
        float2 v2a = __half22float2(u32_to_h2(h2.x));
        float2 v2b = __half22float2(u32_to_h2(h2.y));
        float2 v3a = __half22float2(u32_to_h2(h3.x));
        float2 v3b = __half22float2(u32_to_h2(h3.y));
        a0.x += v0a.x * w0; a0.y += v0a.y * w0; a0.z += v0b.x * w0; a0.w += v0b.y * w0;
        a1.x += v1a.x * w1; a1.y += v1a.y * w1; a1.z += v1b.x * w1; a1.w += v1b.y * w1;
        a2.x += v2a.x * w2; a2.y += v2a.y * w2; a2.z += v2b.x * w2; a2.w += v2b.y * w2;
        a3.x += v3a.x * w3; a3.y += v3a.y * w3; a3.z += v3b.x * w3; a3.w += v3b.y * w3;
    }
    for (; e < end; e++) {
        uint2 p = g_sorted[e];
        uint2 h = *reinterpret_cast<const uint2*>(&g_Th[(size_t)p.x * DIM + lane * 4]);
        float w = __uint_as_float(p.y);
        float2 va = __half22float2(u32_to_h2(h.x));
        float2 vb = __half22float2(u32_to_h2(h.y));
        a0.x += va.x * w; a0.y += va.y * w; a0.z += vb.x * w; a0.w += vb.y * w;
    }

    float4 r;
    r.x = (a0.x + a1.x) + (a2.x + a3.x);
    r.y = (a0.y + a1.y) + (a2.y + a3.y);
    r.z = (a0.z + a1.z) + (a2.z + a3.z);
    r.w = (a0.w + a1.w) + (a2.w + a3.w);
    *reinterpret_cast<float4*>(&out[(size_t)node * DIM + lane * 4]) = r;
}

// ---------------------------------------------------------------------------
// Launch: GEMM runs on a side stream, overlapped with the sort chain on the
// main (capture-origin) stream. Standard fork/join event pattern — legal in
// stream capture; the captured graph encodes the parallelism.
// ---------------------------------------------------------------------------
extern "C" void kernel_launch(void* const* d_in, const int* in_sizes, int n_in,
                              void* d_out, int out_size)
{
    const float* node_emb = (const float*)d_in[0];
    const float* ew       = (const float*)d_in[1];
    const int*   src      = (const int*)d_in[2];
    const int*   dst      = (const int*)d_in[3];
    const float* W        = (const float*)d_in[4];
    float*       out      = (float*)d_out;

    const int n_nodes = in_sizes[0] / DIM;
    const int n_edges = in_sizes[1];

    void* cnt_ptr = nullptr;
    cudaGetSymbolAddress(&cnt_ptr, g_cnt);

    // side stream + fork/join events (host objects only; no device memory)
    cudaStream_t s;
    cudaStreamCreateWithFlags(&s, cudaStreamNonBlocking);
    cudaEvent_t evFork, evJoin;
    cudaEventCreateWithFlags(&evFork, cudaEventDisableTiming);
    cudaEventCreateWithFlags(&evJoin, cudaEventDisableTiming);

    // fork
    cudaEventRecord(evFork, 0);
    cudaStreamWaitEvent(s, evFork, 0);

    // --- side stream: tensor-core transform (independent of edge pipeline) ---
    const int smem_bytes = 2 * 128 * SMS * (int)sizeof(__half);  // 69632
    cudaFuncSetAttribute(transform_mma_kernel,
                         cudaFuncAttributeMaxDynamicSharedMemorySize, smem_bytes);
    int gemm_blocks = (n_nodes + 127) / 128;
    transform_mma_kernel<<<gemm_blocks, 256, smem_bytes, s>>>(node_emb, W, n_nodes);
    cudaEventRecord(evJoin, s);

    // --- main stream: sort pipeline ---
    cudaMemsetAsync(cnt_ptr, 0, (size_t)n_nodes * sizeof(unsigned));
    int eb = (n_edges + 255) / 256;
    hist_kernel<<<eb, 256>>>(dst, n_edges);
    int nchunks = (n_nodes + 1023) / 1024;
    scan1_kernel<<<nchunks, 1024>>>(n_nodes);
    scan2_kernel<<<1, 32>>>(nchunks);
    scan3_kernel<<<nchunks, 1024>>>(n_nodes);
    bucket_kernel<<<eb, 256>>>(src, dst, ew, n_edges);

    // join: agg needs both g_Th (side) and g_sorted/g_off (main)
    cudaStreamWaitEvent(0, evJoin, 0);
    int ab = (n_nodes * 32 + 255) / 256;
    agg_kernel<<<ab, 256>>>(out, n_nodes, n_edges);

    // destroy host objects only when NOT capturing (destroying a stream that
    // participates in an active capture would invalidate the graph)
    cudaStreamCaptureStatus cap = cudaStreamCaptureStatusNone;
    cudaStreamIsCapturing(s, &cap);
    if (cap == cudaStreamCaptureStatusNone) {
        cudaEventDestroy(evFork);
        cudaEventDestroy(evJoin);
        cudaStreamDestroy(s);
    }
}

// round 8
// speedup vs baseline: 2.4956x; 1.0077x over previous
#include <cuda_runtime.h>
#include <cuda_fp16.h>
#include <cstdint>
#include <cstring>

#define N_NODES_MAX 100000
#define EDGE_MAX    1600000
#define DIM 128

// bit-cast helpers (fold to register moves)
__device__ __forceinline__ unsigned h2_to_u32(__half2 h) {
    unsigned u; memcpy(&u, &h, 4); return u;
}
__device__ __forceinline__ __half2 u32_to_h2(unsigned u) {
    __half2 h; memcpy(&h, &u, 4); return h;
}
__device__ __forceinline__ uint32_t smem_u32(const void* p) {
    uint32_t a;
    asm("{ .reg .u64 t; cvta.to.shared.u64 t, %1; cvt.u32.u64 %0, t; }" : "=r"(a) : "l"(p));
    return a;
}

#define LDSM_X4(r0, r1, r2, r3, addr)                                         \
    asm volatile("ldmatrix.sync.aligned.m8n8.x4.shared.b16 {%0,%1,%2,%3}, [%4];" \
                 : "=r"(r0), "=r"(r1), "=r"(r2), "=r"(r3) : "r"(addr))

#define MMA16816(c, a0, a1, a2, a3, b0, b1)                                   \
    asm volatile("mma.sync.aligned.m16n8k16.row.col.f32.f16.f16.f32 "         \
                 "{%0,%1,%2,%3}, {%4,%5,%6,%7}, {%8,%9}, {%0,%1,%2,%3};"      \
                 : "+f"(c[0]), "+f"(c[1]), "+f"(c[2]), "+f"(c[3])             \
                 : "r"(a0), "r"(a1), "r"(a2), "r"(a3), "r"(b0), "r"(b1))

// scratch (allocation-free rule: __device__ globals)
__device__ __half   g_Th[(size_t)N_NODES_MAX * DIM];  // transformed features (fp16)
__device__ unsigned g_cnt[N_NODES_MAX];
__device__ unsigned g_off[N_NODES_MAX];
__device__ unsigned g_cur[N_NODES_MAX];
__device__ unsigned g_bsum[256];
__device__ uint2    g_sorted[EDGE_MAX];               // (src, weight_bits) sorted by dst

// ---------------------------------------------------------------------------
// Kernel 1: T = node_emb @ W^T via HMMA (fp16 in, f32 acc, fp16 out).
// ---------------------------------------------------------------------------
#define SMS 136  // smem row stride in halves

__global__ __launch_bounds__(256, 2)
void transform_mma_kernel(const float* __restrict__ E, const float* __restrict__ W, int n_rows)
{
    extern __shared__ __half sm[];
    __half* As = sm;               // [128][SMS]
    __half* Ws = sm + 128 * SMS;   // [128][SMS]

    const int tid  = threadIdx.x;
    const int row0 = blockIdx.x * 128;

#pragma unroll
    for (int i = 0; i < 16; i++) {
        int idx = tid + i * 256;
        int r   = idx >> 5;
        int c4  = idx & 31;
        float4 v = make_float4(0.f, 0.f, 0.f, 0.f);
        int er = row0 + r;
        if (er < n_rows) v = *reinterpret_cast<const float4*>(&E[(size_t)er * DIM + c4 * 4]);
        uint2 ue = make_uint2(h2_to_u32(__floats2half2_rn(v.x, v.y)),
                              h2_to_u32(__floats2half2_rn(v.z, v.w)));
        *reinterpret_cast<uint2*>(&As[r * SMS + c4 * 4]) = ue;

        float4 wv = *reinterpret_cast<const float4*>(&W[(size_t)r * DIM + c4 * 4]);
        uint2 uw = make_uint2(h2_to_u32(__floats2half2_rn(wv.x, wv.y)),
                              h2_to_u32(__floats2half2_rn(wv.z, wv.w)));
        *reinterpret_cast<uint2*>(&Ws[r * SMS + c4 * 4]) = uw;
    }
    __syncthreads();

    const int lane = tid & 31;
    const int warp = tid >> 5;
    const int r0   = warp * 16;

    uint32_t a_base = smem_u32(&As[(r0 + (lane & 15)) * SMS + ((lane >> 4) * 8)]);
    int brow = (lane & 7) + ((lane & 16) ? 8 : 0);
    int bcol = ((lane >> 3) & 1) * 8;
    uint32_t b_base = smem_u32(&Ws[brow * SMS + bcol]);

    float c[16][4];
#pragma unroll
    for (int j = 0; j < 16; j++)
#pragma unroll
        for (int q = 0; q < 4; q++) c[j][q] = 0.f;

#pragma unroll
    for (int k0 = 0; k0 < 128; k0 += 16) {
        uint32_t a0, a1, a2, a3;
        LDSM_X4(a0, a1, a2, a3, a_base + k0 * 2);
#pragma unroll
        for (int np = 0; np < 8; np++) {
            uint32_t b0, b1, b2, b3;
            LDSM_X4(b0, b1, b2, b3, b_base + (np * 16 * SMS + k0) * 2);
            MMA16816(c[2 * np],     a0, a1, a2, a3, b0, b1);
            MMA16816(c[2 * np + 1], a0, a1, a2, a3, b2, b3);
        }
    }

    const int g = lane >> 2, t = lane & 3;
    const int rowA = row0 + r0 + g;
    const int rowB = rowA + 8;
#pragma unroll
    for (int j = 0; j < 16; j++) {
        __half2 h01 = __floats2half2_rn(c[j][0], c[j][1]);
        __half2 h23 = __floats2half2_rn(c[j][2], c[j][3]);
        int col = j * 8 + 2 * t;
        if (rowA < n_rows)
            *reinterpret_cast<__half2*>(&g_Th[(size_t)rowA * DIM + col]) = h01;
        if (rowB < n_rows)
            *reinterpret_cast<__half2*>(&g_Th[(size_t)rowB * DIM + col]) = h23;
    }
}

// ---------------------------------------------------------------------------
// Sort pipeline: histogram -> scan1 -> scan3(fused base) -> bucket scatter
// ---------------------------------------------------------------------------
__global__ void hist_kernel(const int* __restrict__ dst, int n_edges)
{
    int i = blockIdx.x * blockDim.x + threadIdx.x;
    int e0 = i * 4;
    if (e0 + 4 <= n_edges) {
        int4 d4 = *reinterpret_cast<const int4*>(dst + e0);
        atomicAdd(&g_cnt[d4.x], 1u);
        atomicAdd(&g_cnt[d4.y], 1u);
        atomicAdd(&g_cnt[d4.z], 1u);
        atomicAdd(&g_cnt[d4.w], 1u);
    } else {
        for (int e = e0; e < n_edges; e++) atomicAdd(&g_cnt[dst[e]], 1u);
    }
}

__global__ __launch_bounds__(1024)
void scan1_kernel(int n)
{
    __shared__ unsigned s[1024];
    int i = blockIdx.x * 1024 + threadIdx.x;
    unsigned v = (i < n) ? g_cnt[i] : 0u;
    s[threadIdx.x] = v;
    __syncthreads();
#pragma unroll
    for (int d = 1; d < 1024; d <<= 1) {
        unsigned t = (threadIdx.x >= d) ? s[threadIdx.x - d] : 0u;
        __syncthreads();
        s[threadIdx.x] += t;
        __syncthreads();
    }
    unsigned incl = s[threadIdx.x];
    if (i < n) g_off[i] = incl - v;
    if (threadIdx.x == 1023) g_bsum[blockIdx.x] = incl;
}

// scan3 with fused chunk-base reduction: each block sums g_bsum[0..bid) itself
// (<=98 L2-resident words, warp-strided) -> no serial prescan kernel needed.
__global__ __launch_bounds__(1024)
void scan3_kernel(int n)
{
    __shared__ unsigned sbase;
    int t = threadIdx.x;
    if (t < 32) {
        unsigned s = 0;
        int bid = blockIdx.x;
        for (int b = t; b < bid; b += 32) s += g_bsum[b];
#pragma unroll
        for (int o = 16; o; o >>= 1) s += __shfl_down_sync(0xffffffffu, s, o);
        if (t == 0) sbase = s;
    }
    __syncthreads();
    int i = blockIdx.x * 1024 + t;
    if (i < n) {
        unsigned o = g_off[i] + sbase;
        g_off[i] = o;
        g_cur[i] = o;
    }
}

__global__ void bucket_kernel(const int* __restrict__ src,
                              const int* __restrict__ dst,
                              const float* __restrict__ ew,
                              int n_edges)
{
    int i = blockIdx.x * blockDim.x + threadIdx.x;
    int e0 = i * 4;
    if (e0 + 4 <= n_edges) {
        int4   s4 = *reinterpret_cast<const int4*>(src + e0);
        int4   d4 = *reinterpret_cast<const int4*>(dst + e0);
        float4 w4 = *reinterpret_cast<const float4*>(ew + e0);
        unsigned p0 = atomicAdd(&g_cur[d4.x], 1u);
        unsigned p1 = atomicAdd(&g_cur[d4.y], 1u);
        unsigned p2 = atomicAdd(&g_cur[d4.z], 1u);
        unsigned p3 = atomicAdd(&g_cur[d4.w], 1u);
        g_sorted[p0] = make_uint2((unsigned)s4.x, __float_as_uint(w4.x));
        g_sorted[p1] = make_uint2((unsigned)s4.y, __float_as_uint(w4.y));
        g_sorted[p2] = make_uint2((unsigned)s4.z, __float_as_uint(w4.z));
        g_sorted[p3] = make_uint2((unsigned)s4.w, __float_as_uint(w4.w));
    } else {
        for (int e = e0; e < n_edges; e++) {
            int d = dst[e];
            unsigned pos = atomicAdd(&g_cur[d], 1u);
            g_sorted[pos] = make_uint2((unsigned)src[e], __float_as_uint(ew[e]));
        }
    }
}

// ---------------------------------------------------------------------------
// Aggregation: one warp per dst node; fp16 gather, f32 accumulate
// ---------------------------------------------------------------------------
__global__ __launch_bounds__(256)
void agg_kernel(float* __restrict__ out, int n_nodes, int n_edges)
{
    int node = (int)((blockIdx.x * (unsigned)blockDim.x + threadIdx.x) >> 5);
    int lane = threadIdx.x & 31;
    if (node >= n_nodes) return;

    unsigned start = g_off[node];
    unsigned end   = (node + 1 < n_nodes) ? g_off[node + 1] : (unsigned)n_edges;

    float4 a0 = make_float4(0.f, 0.f, 0.f, 0.f);
    float4 a1 = a0, a2 = a0, a3 = a0;

    unsigned e = start;
    for (; e + 4 <= end; e += 4) {
        uint2 p0 = g_sorted[e + 0];
        uint2 p1 = g_sorted[e + 1];
        uint2 p2 = g_sorted[e + 2];
        uint2 p3 = g_sorted[e + 3];
        uint2 h0 = *reinterpret_cast<const uint2*>(&g_Th[(size_t)p0.x * DIM + lane * 4]);
        uint2 h1 = *reinterpret_cast<const uint2*>(&g_Th[(size_t)p1.x * DIM + lane * 4]);
        uint2 h2 = *reinterpret_cast<const uint2*>(&g_Th[(size_t)p2.x * DIM + lane * 4]);
        uint2 h3 = *reinterpret_cast<const uint2*>(&g_Th[(size_t)p3.x * DIM + lane * 4]);
        float w0 = __uint_as_float(p0.y), w1 = __uint_as_float(p1.y);
        float w2 = __uint_as_float(p2.y), w3 = __uint_as_float(p3.y);
        float2 v0a = __half22float2(u32_to_h2(h0.x));
        float2 v0b = __half22float2(u32_to_h2(h0.y));
        float2 v1a = __half22float2(u32_to_h2(h1.x));
        float2 v1b = __half22float2(u32_to_h2(h1.y));
        float2 v2a = __half22float2(u32_to_h2(h2.x));
        float2 v2b = __half22float2(u32_to_h2(h2.y));
        float2 v3a = __half22float2(u32_to_h2(h3.x));
        float2 v3b = __half22float2(u32_to_h2(h3.y));
        a0.x += v0a.x * w0; a0.y += v0a.y * w0; a0.z += v0b.x * w0; a0.w += v0b.y * w0;
        a1.x += v1a.x * w1; a1.y += v1a.y * w1; a1.z += v1b.x * w1; a1.w += v1b.y * w1;
        a2.x += v2a.x * w2; a2.y += v2a.y * w2; a2.z += v2b.x * w2; a2.w += v2b.y * w2;
        a3.x += v3a.x * w3; a3.y += v3a.y * w3; a3.z += v3b.x * w3; a3.w += v3b.y * w3;
    }
    for (; e < end; e++) {
        uint2 p = g_sorted[e];
        uint2 h = *reinterpret_cast<const uint2*>(&g_Th[(size_t)p.x * DIM + lane * 4]);
        float w = __uint_as_float(p.y);
        float2 va = __half22float2(u32_to_h2(h.x));
        float2 vb = __half22float2(u32_to_h2(h.y));
        a0.x += va.x * w; a0.y += va.y * w; a0.z += vb.x * w; a0.w += vb.y * w;
    }

    float4 r;
    r.x = (a0.x + a1.x) + (a2.x + a3.x);
    r.y = (a0.y + a1.y) + (a2.y + a3.y);
    r.z = (a0.z + a1.z) + (a2.z + a3.z);
    r.w = (a0.w + a1.w) + (a2.w + a3.w);
    *reinterpret_cast<float4*>(&out[(size_t)node * DIM + lane * 4]) = r;
}

// ---------------------------------------------------------------------------
// Launch: GEMM on a side stream overlapped with the sort chain (fork/join).
// ---------------------------------------------------------------------------
extern "C" void kernel_launch(void* const* d_in, const int* in_sizes, int n_in,
                              void* d_out, int out_size)
{
    const float* node_emb = (const float*)d_in[0];
    const float* ew       = (const float*)d_in[1];
    const int*   src      = (const int*)d_in[2];
    const int*   dst      = (const int*)d_in[3];
    const float* W        = (const float*)d_in[4];
    float*       out      = (float*)d_out;

    const int n_nodes = in_sizes[0] / DIM;
    const int n_edges = in_sizes[1];

    void* cnt_ptr = nullptr;
    cudaGetSymbolAddress(&cnt_ptr, g_cnt);

    cudaStream_t s;
    cudaStreamCreateWithFlags(&s, cudaStreamNonBlocking);
    cudaEvent_t evFork, evJoin;
    cudaEventCreateWithFlags(&evFork, cudaEventDisableTiming);
    cudaEventCreateWithFlags(&evJoin, cudaEventDisableTiming);

    cudaEventRecord(evFork, 0);
    cudaStreamWaitEvent(s, evFork, 0);

    // --- side stream: tensor-core transform ---
    const int smem_bytes = 2 * 128 * SMS * (int)sizeof(__half);  // 69632
    cudaFuncSetAttribute(transform_mma_kernel,
                         cudaFuncAttributeMaxDynamicSharedMemorySize, smem_bytes);
    int gemm_blocks = (n_nodes + 127) / 128;
    transform_mma_kernel<<<gemm_blocks, 256, smem_bytes, s>>>(node_emb, W, n_nodes);
    cudaEventRecord(evJoin, s);

    // --- main stream: sort pipeline (scan2 eliminated) ---
    cudaMemsetAsync(cnt_ptr, 0, (size_t)n_nodes * sizeof(unsigned));
    int eb4 = (n_edges / 4 + 255) / 256 + 1;
    hist_kernel<<<eb4, 256>>>(dst, n_edges);
    int nchunks = (n_nodes + 1023) / 1024;
    scan1_kernel<<<nchunks, 1024>>>(n_nodes);
    scan3_kernel<<<nchunks, 1024>>>(n_nodes);
    bucket_kernel<<<eb4, 256>>>(src, dst, ew, n_edges);

    cudaStreamWaitEvent(0, evJoin, 0);
    int ab = (n_nodes * 32 + 255) / 256;
    agg_kernel<<<ab, 256>>>(out, n_nodes, n_edges);

    cudaStreamCaptureStatus cap = cudaStreamCaptureStatusNone;
    cudaStreamIsCapturing(s, &cap);
    if (cap == cudaStreamCaptureStatusNone) {
        cudaEventDestroy(evFork);
        cudaEventDestroy(evJoin);
        cudaStreamDestroy(s);
    }
}